// round 16
// baseline (speedup 1.0000x reference)
#include <cuda_runtime.h>
#include <cstdint>

// Problem constants
#define Bz 8
#define Tz 1024
#define Dz 1024
#define Qz 8
#define Kz 4096
#define dz 128
#define Mz (Bz*Tz)               // 8192 rows
#define OUT_ELEMS (Mz*Dz)        // 8388608
#define IDX_ELEMS (Mz*Qz)        // 65536

// Scratch (device globals: allocation-free rule)
__device__ float  g_xn[(size_t)Mz*Dz];        // rmsnorm'd input, 32MB
__device__ float  g_hc2[Qz*Kz];               // 0.5 * ||code||^2
__device__ float2 g_pb[(size_t)Mz*Qz*4];      // per-quarter partial (val, idx-bits)

// ---- f32x2 packed-FMA helpers (sm_103a FFMA2) ----
static __device__ __forceinline__ unsigned long long pack2(float v){
    unsigned long long r; unsigned u = __float_as_uint(v);
    asm("mov.b64 %0, {%1, %1};" : "=l"(r) : "r"(u));
    return r;
}
static __device__ __forceinline__ void ffma2(unsigned long long& d,
                                             unsigned long long a,
                                             unsigned long long b){
    asm("fma.rn.f32x2 %0, %1, %2, %0;" : "+l"(d) : "l"(a), "l"(b));
}
static __device__ __forceinline__ float2 unpack2(unsigned long long v){
    unsigned lo, hi;
    asm("mov.b64 {%0, %1}, %2;" : "=r"(lo), "=r"(hi) : "l"(v));
    return make_float2(__uint_as_float(lo), __uint_as_float(hi));
}

// ---------------- Kernel 1: fused input rmsnorm + hc2 ----------------
// blocks [0, 8192): rmsnorm row m = blockIdx.x
// blocks [8192, 12288): 0.5*||code||^2 for codes (blockIdx.x-8192)*8 + warp
__global__ void prep_kernel(const float* __restrict__ x,
                            const float* __restrict__ w,
                            const float* __restrict__ cb){
    int b = blockIdx.x, t = threadIdx.x;
    if (b < Mz){
        int m = b;
        float4 v = reinterpret_cast<const float4*>(x)[(size_t)m*256 + t];
        float ss = v.x*v.x + v.y*v.y + v.z*v.z + v.w*v.w;
        __shared__ float sred[8];
        __shared__ float s_scale;
        #pragma unroll
        for (int o = 16; o > 0; o >>= 1) ss += __shfl_xor_sync(0xffffffffu, ss, o);
        if ((t & 31) == 0) sred[t >> 5] = ss;
        __syncthreads();
        if (t < 8){
            float s2 = sred[t];
            #pragma unroll
            for (int o = 4; o > 0; o >>= 1) s2 += __shfl_xor_sync(0xffu, s2, o);
            if (t == 0){
                float mean = s2 * (1.0f/1024.0f) + 1e-5f;
                float r = rsqrtf(mean);
                r = r * (1.5f - 0.5f*mean*r*r);   // one Newton step
                s_scale = r;
            }
        }
        __syncthreads();
        float sc = s_scale;
        float4 wv = reinterpret_cast<const float4*>(w)[t];
        float4 o4 = make_float4(v.x*sc*wv.x, v.y*sc*wv.y, v.z*sc*wv.z, v.w*sc*wv.w);
        reinterpret_cast<float4*>(g_xn)[(size_t)m*256 + t] = o4;
    } else {
        int code = (b - Mz)*8 + (t >> 5);
        int lane = t & 31;
        float4 c = reinterpret_cast<const float4*>(cb)[(size_t)code*32 + lane];
        float s = c.x*c.x + c.y*c.y + c.z*c.z + c.w*c.w;
        #pragma unroll
        for (int o = 16; o > 0; o >>= 1) s += __shfl_xor_sync(0xffffffffu, s, o);
        if (lane == 0) g_hc2[code] = 0.5f*s;
    }
}

// ---------------- Kernel 2: fused GEMM + argmax(xc - 0.5c2), col-quartered ----
// Block = (128-row mtile, 1024-col quarter, q): blockIdx.x = mt*4 + qt.
// 2048 tasks -> 7 waves on 296 slots (98.8% util). Microkernel: 8x8 f32x2
// outer product, broadcast A, reg-staged double-buffered B. Epilogue:
// predicated compare-update (branch-free; strict > keeps lowest idx).
#define SA   132                   // As row-dim stride (words); STS conflict-free
#define BSTR 192                   // B k-row stride (words); 16 groups * 12
#define SMEM_ARGMIN (128*SA*4 + 2*16*BSTR*4)   // 67584 + 24576 = 92160

static __device__ __forceinline__ int bcol(int c){ return 12*(c>>3) + (c&7); }

__global__ void __launch_bounds__(256, 2)
argmin_kernel(const float* __restrict__ cb){
    extern __shared__ float sm[];
    float* As = sm;
    float* B0 = sm + 128*SA;
    float* B1 = B0 + 16*BSTR;

    int tid = threadIdx.x;
    int tx = tid & 15, ty = tid >> 4;
    int q  = blockIdx.y;
    int bx = blockIdx.x;
    int mt = bx >> 2, qt = bx & 3;
    int m0 = mt*128;
    int qb = qt*1024;                                  // column-quarter base

    const float* xq  = g_xn + (size_t)m0*Dz + q*dz;
    const float* cbq = cb + (size_t)q*Kz*dz + (size_t)qb*dz;
    const float* hcq = g_hc2 + q*Kz + qb;

    // ---- A tile: 128 rows x 128 k, transposed As[k][row]. One-time load.
    #pragma unroll
    for (int it = 0; it < 16; ++it){
        int u  = it*256 + tid;
        int kk = (u & 31) + ((u >> 10) << 5);
        int rg = (u >> 5) & 31;
        const float* p = xq + (size_t)(4*rg)*Dz + kk;
        float a0 = p[0], a1 = p[Dz], a2 = p[2*Dz], a3 = p[3*Dz];
        *reinterpret_cast<float4*>(&As[kk*SA + 4*rg]) = make_float4(a0,a1,a2,a3);
    }

    // per-thread B staging: 2 float4 per iteration (128 cols x 16 k / 256 thr)
    int pks0 = tid & 3,         pcol0 = tid >> 2;
    int pks1 = (256+tid) & 3,   pcol1 = (256+tid) >> 2;
    int bc0 = bcol(pcol0), bc1 = bcol(pcol1);

    // prologue: load + store B for iteration 0 into B0
    float4 pre0 = *reinterpret_cast<const float4*>(cbq + (size_t)pcol0*dz + 4*pks0);
    float4 pre1 = *reinterpret_cast<const float4*>(cbq + (size_t)pcol1*dz + 4*pks1);
    B0[(4*pks0+0)*BSTR + bc0] = pre0.x;  B0[(4*pks0+1)*BSTR + bc0] = pre0.y;
    B0[(4*pks0+2)*BSTR + bc0] = pre0.z;  B0[(4*pks0+3)*BSTR + bc0] = pre0.w;
    B0[(4*pks1+0)*BSTR + bc1] = pre1.x;  B0[(4*pks1+1)*BSTR + bc1] = pre1.y;
    B0[(4*pks1+2)*BSTR + bc1] = pre1.z;  B0[(4*pks1+3)*BSTR + bc1] = pre1.w;
    __syncthreads();

    unsigned long long acc[4][8];    // [row-pair][col]; rows 8*ty+2p, 8*ty+2p+1
    float bestv[8];
    int   besti[8];
    #pragma unroll
    for (int i = 0; i < 8; ++i){ bestv[i] = -3.4e38f; besti[i] = 0; }

    for (int it = 0; it < 64; ++it){            // it = chunk*8 + kc ; 8 chunks of 128 cols
        int c = it >> 3, kc = it & 7;

        // prefetch next B sub-tile into registers (hidden under compute)
        if (it + 1 < 64){
            int nc = (it+1) >> 3, nkc = (it+1) & 7;
            const float* bg = cbq + (size_t)nc*128*dz + nkc*16;
            pre0 = *reinterpret_cast<const float4*>(bg + (size_t)pcol0*dz + 4*pks0);
            pre1 = *reinterpret_cast<const float4*>(bg + (size_t)pcol1*dz + 4*pks1);
        }

        // chunk start: acc <- -0.5*||c||^2 (argmax form)
        if (kc == 0){
            float4 h0 = *reinterpret_cast<const float4*>(hcq + c*128 + 8*tx);
            float4 h1 = *reinterpret_cast<const float4*>(hcq + c*128 + 8*tx + 4);
            unsigned long long hp[8];
            hp[0]=pack2(-h0.x); hp[1]=pack2(-h0.y); hp[2]=pack2(-h0.z); hp[3]=pack2(-h0.w);
            hp[4]=pack2(-h1.x); hp[5]=pack2(-h1.y); hp[6]=pack2(-h1.z); hp[7]=pack2(-h1.w);
            #pragma unroll
            for (int p = 0; p < 4; ++p)
                #pragma unroll
                for (int j = 0; j < 8; ++j) acc[p][j] = hp[j];
        }

        const float* Bc = (it & 1) ? B1 : B0;
        const float* Ab = As + (kc*16)*SA + 8*ty;
        const float* Bb = Bc + 12*tx;

        #pragma unroll
        for (int k = 0; k < 16; ++k){
            ulonglong2 a0 = *reinterpret_cast<const ulonglong2*>(Ab + k*SA);      // rows 0-3
            ulonglong2 a1 = *reinterpret_cast<const ulonglong2*>(Ab + k*SA + 4);  // rows 4-7
            float4 b0 = *reinterpret_cast<const float4*>(Bb + k*BSTR);
            float4 b1 = *reinterpret_cast<const float4*>(Bb + k*BSTR + 4);
            unsigned long long bb0 = pack2(b0.x), bb1 = pack2(b0.y);
            unsigned long long bb2 = pack2(b0.z), bb3 = pack2(b0.w);
            unsigned long long bb4 = pack2(b1.x), bb5 = pack2(b1.y);
            unsigned long long bb6 = pack2(b1.z), bb7 = pack2(b1.w);
            ffma2(acc[0][0], a0.x, bb0); ffma2(acc[1][0], a0.y, bb0);
            ffma2(acc[2][0], a1.x, bb0); ffma2(acc[3][0], a1.y, bb0);
            ffma2(acc[0][1], a0.x, bb1); ffma2(acc[1][1], a0.y, bb1);
            ffma2(acc[2][1], a1.x, bb1); ffma2(acc[3][1], a1.y, bb1);
            ffma2(acc[0][2], a0.x, bb2); ffma2(acc[1][2], a0.y, bb2);
            ffma2(acc[2][2], a1.x, bb2); ffma2(acc[3][2], a1.y, bb2);
            ffma2(acc[0][3], a0.x, bb3); ffma2(acc[1][3], a0.y, bb3);
            ffma2(acc[2][3], a1.x, bb3); ffma2(acc[3][3], a1.y, bb3);
            ffma2(acc[0][4], a0.x, bb4); ffma2(acc[1][4], a0.y, bb4);
            ffma2(acc[2][4], a1.x, bb4); ffma2(acc[3][4], a1.y, bb4);
            ffma2(acc[0][5], a0.x, bb5); ffma2(acc[1][5], a0.y, bb5);
            ffma2(acc[2][5], a1.x, bb5); ffma2(acc[3][5], a1.y, bb5);
            ffma2(acc[0][6], a0.x, bb6); ffma2(acc[1][6], a0.y, bb6);
            ffma2(acc[2][6], a1.x, bb6); ffma2(acc[3][6], a1.y, bb6);
            ffma2(acc[0][7], a0.x, bb7); ffma2(acc[1][7], a0.y, bb7);
            ffma2(acc[2][7], a1.x, bb7); ffma2(acc[3][7], a1.y, bb7);
        }

        // drain staged regs into the other buffer
        if (it + 1 < 64){
            float* Bn = ((it+1) & 1) ? B1 : B0;
            Bn[(4*pks0+0)*BSTR + bc0] = pre0.x;  Bn[(4*pks0+1)*BSTR + bc0] = pre0.y;
            Bn[(4*pks0+2)*BSTR + bc0] = pre0.z;  Bn[(4*pks0+3)*BSTR + bc0] = pre0.w;
            Bn[(4*pks1+0)*BSTR + bc1] = pre1.x;  Bn[(4*pks1+1)*BSTR + bc1] = pre1.y;
            Bn[(4*pks1+2)*BSTR + bc1] = pre1.z;  Bn[(4*pks1+3)*BSTR + bc1] = pre1.w;
        }

        // chunk end: fold acc into running argmax (strict > keeps lowest idx)
        if (kc == 7){
            int n0 = qb + c*128 + 8*tx;
            #pragma unroll
            for (int p = 0; p < 4; ++p)
                #pragma unroll
                for (int j = 0; j < 8; ++j){
                    float2 v = unpack2(acc[p][j]);
                    if (v.x > bestv[2*p])   { bestv[2*p]   = v.x; besti[2*p]   = n0 + j; }
                    if (v.y > bestv[2*p+1]) { bestv[2*p+1] = v.y; besti[2*p+1] = n0 + j; }
                }
        }
        __syncthreads();
    }

    // Cross-thread reduction: 16 tx candidates per row; max, tie -> lower idx
    float* rv = sm;                                    // 128*16 floats
    int*   ri = reinterpret_cast<int*>(sm + 128*16);   // 128*16 ints
    #pragma unroll
    for (int i = 0; i < 8; ++i){
        int row = 8*ty + i;
        rv[row*16 + tx] = bestv[i];
        ri[row*16 + tx] = besti[i];
    }
    __syncthreads();
    if (tid < 128){
        float bv = rv[tid*16]; int bi = ri[tid*16];
        #pragma unroll
        for (int t2 = 1; t2 < 16; ++t2){
            float v = rv[tid*16 + t2]; int id = ri[tid*16 + t2];
            if (v > bv || (v == bv && id < bi)) { bv = v; bi = id; }
        }
        int m = m0 + tid;
        g_pb[((size_t)m*Qz + q)*4 + qt] = make_float2(bv, __int_as_float(bi));
    }
}

// ---------------- Kernel 3: merge quarters + gather + output rmsnorm --------
__global__ void out_kernel(const float* __restrict__ cb,
                           const float* __restrict__ w,
                           float* __restrict__ out,
                           float* __restrict__ tail){
    int m = blockIdx.x, t = threadIdx.x;
    __shared__ int   sidx[8];
    __shared__ float s_scale;
    if (t < 8){
        // merge 4 column-quarter partials (quarters ascend -> tie to lower idx)
        const float2* pb = g_pb + ((size_t)m*Qz + t)*4;
        float2 p0 = pb[0];
        float bv = p0.x; int bi = __float_as_int(p0.y);
        #pragma unroll
        for (int qt = 1; qt < 4; ++qt){
            float2 p = pb[qt];
            int id = __float_as_int(p.y);
            if (p.x > bv || (p.x == bv && id < bi)) { bv = p.x; bi = id; }
        }
        sidx[t] = bi;
        if (tail) tail[m*Qz + t] = (float)bi;
    }
    __syncthreads();
    if (t < 8){
        float p = g_hc2[t*Kz + sidx[t]];
        #pragma unroll
        for (int o = 4; o > 0; o >>= 1) p += __shfl_xor_sync(0xffu, p, o);
        if (t == 0){
            float mean = (2.0f*p) * (1.0f/1024.0f) + 1e-5f;
            float r = rsqrtf(mean);
            r = r * (1.5f - 0.5f*mean*r*r);
            s_scale = r;
        }
    }
    __syncthreads();
    int q = t >> 5, lane = t & 31;
    float4 c = reinterpret_cast<const float4*>(cb)[((size_t)q*Kz + sidx[q])*32 + lane];
    float sc = s_scale;
    float4 wv = reinterpret_cast<const float4*>(w)[t];
    reinterpret_cast<float4*>(out)[(size_t)m*256 + t] =
        make_float4(c.x*sc*wv.x, c.y*sc*wv.y, c.z*sc*wv.z, c.w*sc*wv.w);
}

// ---------------- Launch ----------------
extern "C" void kernel_launch(void* const* d_in, const int* in_sizes, int n_in,
                              void* d_out, int out_size){
    const float* x     = (const float*)d_in[0];
    const float* cb    = (const float*)d_in[1];
    const float* w_in  = (const float*)d_in[2];
    const float* w_out = (const float*)d_in[3];
    float* out = (float*)d_out;
    float* tail = (out_size >= OUT_ELEMS + IDX_ELEMS) ? (out + OUT_ELEMS) : nullptr;

    cudaFuncSetAttribute((const void*)argmin_kernel,
                         cudaFuncAttributeMaxDynamicSharedMemorySize, SMEM_ARGMIN);

    prep_kernel<<<Mz + (Qz*Kz)/8, 256>>>(x, w_in, cb);
    argmin_kernel<<<dim3((Mz/128)*4, Qz), 256, SMEM_ARGMIN>>>(cb);
    out_kernel<<<Mz, 256>>>(cb, w_out, out, tail);
}

// round 17
// speedup vs baseline: 1.0041x; 1.0041x over previous
#include <cuda_runtime.h>
#include <cstdint>

// Problem constants
#define Bz 8
#define Tz 1024
#define Dz 1024
#define Qz 8
#define Kz 4096
#define dz 128
#define Mz (Bz*Tz)               // 8192 rows
#define OUT_ELEMS (Mz*Dz)        // 8388608
#define IDX_ELEMS (Mz*Qz)        // 65536

// Scratch (device globals: allocation-free rule)
__device__ float  g_scale[Mz];                // per-row rmsnorm scale
__device__ float  g_hc2[Qz*Kz];               // 0.5 * ||code||^2
__device__ float2 g_pb[(size_t)Mz*Qz*4];      // per-quarter partial (val, idx-bits)

// ---- f32x2 packed-FMA helpers (sm_103a FFMA2) ----
static __device__ __forceinline__ unsigned long long pack2(float v){
    unsigned long long r; unsigned u = __float_as_uint(v);
    asm("mov.b64 %0, {%1, %1};" : "=l"(r) : "r"(u));
    return r;
}
static __device__ __forceinline__ void ffma2(unsigned long long& d,
                                             unsigned long long a,
                                             unsigned long long b){
    asm("fma.rn.f32x2 %0, %1, %2, %0;" : "+l"(d) : "l"(a), "l"(b));
}
static __device__ __forceinline__ float2 unpack2(unsigned long long v){
    unsigned lo, hi;
    asm("mov.b64 {%0, %1}, %2;" : "=r"(lo), "=r"(hi) : "l"(v));
    return make_float2(__uint_as_float(lo), __uint_as_float(hi));
}

// ---------------- Kernel 1: fused rmsnorm-scale + hc2 ----------------
// blocks [0, 8192): per-row rmsnorm scale only (no 32MB xn write)
// blocks [8192, 12288): 0.5*||code||^2 for codes (blockIdx.x-8192)*8 + warp
__global__ void prep_kernel(const float* __restrict__ x,
                            const float* __restrict__ cb){
    int b = blockIdx.x, t = threadIdx.x;
    if (b < Mz){
        int m = b;
        float4 v = reinterpret_cast<const float4*>(x)[(size_t)m*256 + t];
        float ss = v.x*v.x + v.y*v.y + v.z*v.z + v.w*v.w;
        __shared__ float sred[8];
        #pragma unroll
        for (int o = 16; o > 0; o >>= 1) ss += __shfl_xor_sync(0xffffffffu, ss, o);
        if ((t & 31) == 0) sred[t >> 5] = ss;
        __syncthreads();
        if (t < 8){
            float s2 = sred[t];
            #pragma unroll
            for (int o = 4; o > 0; o >>= 1) s2 += __shfl_xor_sync(0xffu, s2, o);
            if (t == 0){
                float mean = s2 * (1.0f/1024.0f) + 1e-5f;
                float r = rsqrtf(mean);
                r = r * (1.5f - 0.5f*mean*r*r);   // one Newton step (same as before)
                g_scale[m] = r;
            }
        }
    } else {
        int code = (b - Mz)*8 + (t >> 5);
        int lane = t & 31;
        float4 c = reinterpret_cast<const float4*>(cb)[(size_t)code*32 + lane];
        float s = c.x*c.x + c.y*c.y + c.z*c.z + c.w*c.w;
        #pragma unroll
        for (int o = 16; o > 0; o >>= 1) s += __shfl_xor_sync(0xffffffffu, s, o);
        if (lane == 0) g_hc2[code] = 0.5f*s;
    }
}

// ---------------- Kernel 2: fused GEMM + argmax(xc - 0.5c2), col-quartered ----
// Block = (128-row mtile, 1024-col quarter, q): blockIdx.x = mt*4 + qt.
// 2048 tasks -> 7 waves on 296 slots (98.8% util). Microkernel: 8x8 f32x2
// outer product, broadcast A, reg-staged double-buffered B. A is normalized
// on the fly during staging: (x*scale)*w, same association as before ->
// bit-identical A values. Epilogue: predicated compare-update.
#define SA   132                   // As row-dim stride (words); STS conflict-free
#define BSTR 192                   // B k-row stride (words); 16 groups * 12
#define SMEM_ARGMIN (128*SA*4 + 2*16*BSTR*4)   // 67584 + 24576 = 92160

static __device__ __forceinline__ int bcol(int c){ return 12*(c>>3) + (c&7); }

__global__ void __launch_bounds__(256, 2)
argmin_kernel(const float* __restrict__ x,
              const float* __restrict__ w,
              const float* __restrict__ cb){
    extern __shared__ float sm[];
    float* As = sm;
    float* B0 = sm + 128*SA;
    float* B1 = B0 + 16*BSTR;

    int tid = threadIdx.x;
    int tx = tid & 15, ty = tid >> 4;
    int q  = blockIdx.y;
    int bx = blockIdx.x;
    int mt = bx >> 2, qt = bx & 3;
    int m0 = mt*128;
    int qb = qt*1024;                                  // column-quarter base

    const float* xq  = x + (size_t)m0*Dz + q*dz;
    const float* cbq = cb + (size_t)q*Kz*dz + (size_t)qb*dz;
    const float* hcq = g_hc2 + q*Kz + qb;

    // ---- A tile: 128 rows x 128 k, transposed As[k][row], normalized on the
    // fly: (x * row_scale) * w[q*128+kk]. One-time load.
    #pragma unroll
    for (int it = 0; it < 16; ++it){
        int u  = it*256 + tid;
        int kk = (u & 31) + ((u >> 10) << 5);
        int rg = (u >> 5) & 31;
        const float* p = xq + (size_t)(4*rg)*Dz + kk;
        float wv = __ldg(w + q*dz + kk);
        float s0 = __ldg(g_scale + m0 + 4*rg);
        float s1 = __ldg(g_scale + m0 + 4*rg + 1);
        float s2 = __ldg(g_scale + m0 + 4*rg + 2);
        float s3 = __ldg(g_scale + m0 + 4*rg + 3);
        float a0 = (p[0]*s0)*wv, a1 = (p[Dz]*s1)*wv;
        float a2 = (p[2*Dz]*s2)*wv, a3 = (p[3*Dz]*s3)*wv;
        *reinterpret_cast<float4*>(&As[kk*SA + 4*rg]) = make_float4(a0,a1,a2,a3);
    }

    // per-thread B staging: 2 float4 per iteration (128 cols x 16 k / 256 thr)
    int pks0 = tid & 3,         pcol0 = tid >> 2;
    int pks1 = (256+tid) & 3,   pcol1 = (256+tid) >> 2;
    int bc0 = bcol(pcol0), bc1 = bcol(pcol1);

    // prologue: load + store B for iteration 0 into B0
    float4 pre0 = *reinterpret_cast<const float4*>(cbq + (size_t)pcol0*dz + 4*pks0);
    float4 pre1 = *reinterpret_cast<const float4*>(cbq + (size_t)pcol1*dz + 4*pks1);
    B0[(4*pks0+0)*BSTR + bc0] = pre0.x;  B0[(4*pks0+1)*BSTR + bc0] = pre0.y;
    B0[(4*pks0+2)*BSTR + bc0] = pre0.z;  B0[(4*pks0+3)*BSTR + bc0] = pre0.w;
    B0[(4*pks1+0)*BSTR + bc1] = pre1.x;  B0[(4*pks1+1)*BSTR + bc1] = pre1.y;
    B0[(4*pks1+2)*BSTR + bc1] = pre1.z;  B0[(4*pks1+3)*BSTR + bc1] = pre1.w;
    __syncthreads();

    unsigned long long acc[4][8];    // [row-pair][col]; rows 8*ty+2p, 8*ty+2p+1
    float bestv[8];
    int   besti[8];
    #pragma unroll
    for (int i = 0; i < 8; ++i){ bestv[i] = -3.4e38f; besti[i] = 0; }

    for (int it = 0; it < 64; ++it){            // it = chunk*8 + kc ; 8 chunks of 128 cols
        int c = it >> 3, kc = it & 7;

        // prefetch next B sub-tile into registers (hidden under compute)
        if (it + 1 < 64){
            int nc = (it+1) >> 3, nkc = (it+1) & 7;
            const float* bg = cbq + (size_t)nc*128*dz + nkc*16;
            pre0 = *reinterpret_cast<const float4*>(bg + (size_t)pcol0*dz + 4*pks0);
            pre1 = *reinterpret_cast<const float4*>(bg + (size_t)pcol1*dz + 4*pks1);
        }

        // chunk start: acc <- -0.5*||c||^2 (argmax form)
        if (kc == 0){
            float4 h0 = *reinterpret_cast<const float4*>(hcq + c*128 + 8*tx);
            float4 h1 = *reinterpret_cast<const float4*>(hcq + c*128 + 8*tx + 4);
            unsigned long long hp[8];
            hp[0]=pack2(-h0.x); hp[1]=pack2(-h0.y); hp[2]=pack2(-h0.z); hp[3]=pack2(-h0.w);
            hp[4]=pack2(-h1.x); hp[5]=pack2(-h1.y); hp[6]=pack2(-h1.z); hp[7]=pack2(-h1.w);
            #pragma unroll
            for (int p = 0; p < 4; ++p)
                #pragma unroll
                for (int j = 0; j < 8; ++j) acc[p][j] = hp[j];
        }

        const float* Bc = (it & 1) ? B1 : B0;
        const float* Ab = As + (kc*16)*SA + 8*ty;
        const float* Bb = Bc + 12*tx;

        #pragma unroll
        for (int k = 0; k < 16; ++k){
            ulonglong2 a0 = *reinterpret_cast<const ulonglong2*>(Ab + k*SA);      // rows 0-3
            ulonglong2 a1 = *reinterpret_cast<const ulonglong2*>(Ab + k*SA + 4);  // rows 4-7
            float4 b0 = *reinterpret_cast<const float4*>(Bb + k*BSTR);
            float4 b1 = *reinterpret_cast<const float4*>(Bb + k*BSTR + 4);
            unsigned long long bb0 = pack2(b0.x), bb1 = pack2(b0.y);
            unsigned long long bb2 = pack2(b0.z), bb3 = pack2(b0.w);
            unsigned long long bb4 = pack2(b1.x), bb5 = pack2(b1.y);
            unsigned long long bb6 = pack2(b1.z), bb7 = pack2(b1.w);
            ffma2(acc[0][0], a0.x, bb0); ffma2(acc[1][0], a0.y, bb0);
            ffma2(acc[2][0], a1.x, bb0); ffma2(acc[3][0], a1.y, bb0);
            ffma2(acc[0][1], a0.x, bb1); ffma2(acc[1][1], a0.y, bb1);
            ffma2(acc[2][1], a1.x, bb1); ffma2(acc[3][1], a1.y, bb1);
            ffma2(acc[0][2], a0.x, bb2); ffma2(acc[1][2], a0.y, bb2);
            ffma2(acc[2][2], a1.x, bb2); ffma2(acc[3][2], a1.y, bb2);
            ffma2(acc[0][3], a0.x, bb3); ffma2(acc[1][3], a0.y, bb3);
            ffma2(acc[2][3], a1.x, bb3); ffma2(acc[3][3], a1.y, bb3);
            ffma2(acc[0][4], a0.x, bb4); ffma2(acc[1][4], a0.y, bb4);
            ffma2(acc[2][4], a1.x, bb4); ffma2(acc[3][4], a1.y, bb4);
            ffma2(acc[0][5], a0.x, bb5); ffma2(acc[1][5], a0.y, bb5);
            ffma2(acc[2][5], a1.x, bb5); ffma2(acc[3][5], a1.y, bb5);
            ffma2(acc[0][6], a0.x, bb6); ffma2(acc[1][6], a0.y, bb6);
            ffma2(acc[2][6], a1.x, bb6); ffma2(acc[3][6], a1.y, bb6);
            ffma2(acc[0][7], a0.x, bb7); ffma2(acc[1][7], a0.y, bb7);
            ffma2(acc[2][7], a1.x, bb7); ffma2(acc[3][7], a1.y, bb7);
        }

        // drain staged regs into the other buffer
        if (it + 1 < 64){
            float* Bn = ((it+1) & 1) ? B1 : B0;
            Bn[(4*pks0+0)*BSTR + bc0] = pre0.x;  Bn[(4*pks0+1)*BSTR + bc0] = pre0.y;
            Bn[(4*pks0+2)*BSTR + bc0] = pre0.z;  Bn[(4*pks0+3)*BSTR + bc0] = pre0.w;
            Bn[(4*pks1+0)*BSTR + bc1] = pre1.x;  Bn[(4*pks1+1)*BSTR + bc1] = pre1.y;
            Bn[(4*pks1+2)*BSTR + bc1] = pre1.z;  Bn[(4*pks1+3)*BSTR + bc1] = pre1.w;
        }

        // chunk end: fold acc into running argmax (strict > keeps lowest idx)
        if (kc == 7){
            int n0 = qb + c*128 + 8*tx;
            #pragma unroll
            for (int p = 0; p < 4; ++p)
                #pragma unroll
                for (int j = 0; j < 8; ++j){
                    float2 v = unpack2(acc[p][j]);
                    if (v.x > bestv[2*p])   { bestv[2*p]   = v.x; besti[2*p]   = n0 + j; }
                    if (v.y > bestv[2*p+1]) { bestv[2*p+1] = v.y; besti[2*p+1] = n0 + j; }
                }
        }
        __syncthreads();
    }

    // Cross-thread reduction: 16 tx candidates per row; max, tie -> lower idx
    float* rv = sm;                                    // 128*16 floats
    int*   ri = reinterpret_cast<int*>(sm + 128*16);   // 128*16 ints
    #pragma unroll
    for (int i = 0; i < 8; ++i){
        int row = 8*ty + i;
        rv[row*16 + tx] = bestv[i];
        ri[row*16 + tx] = besti[i];
    }
    __syncthreads();
    if (tid < 128){
        float bv = rv[tid*16]; int bi = ri[tid*16];
        #pragma unroll
        for (int t2 = 1; t2 < 16; ++t2){
            float v = rv[tid*16 + t2]; int id = ri[tid*16 + t2];
            if (v > bv || (v == bv && id < bi)) { bv = v; bi = id; }
        }
        int m = m0 + tid;
        g_pb[((size_t)m*Qz + q)*4 + qt] = make_float2(bv, __int_as_float(bi));
    }
}

// ---------------- Kernel 3: merge quarters + gather + output rmsnorm --------
__global__ void out_kernel(const float* __restrict__ cb,
                           const float* __restrict__ w,
                           float* __restrict__ out,
                           float* __restrict__ tail){
    int m = blockIdx.x, t = threadIdx.x;
    __shared__ int   sidx[8];
    __shared__ float s_scale;
    if (t < 8){
        // merge 4 column-quarter partials (quarters ascend -> tie to lower idx)
        const float2* pb = g_pb + ((size_t)m*Qz + t)*4;
        float2 p0 = pb[0];
        float bv = p0.x; int bi = __float_as_int(p0.y);
        #pragma unroll
        for (int qt = 1; qt < 4; ++qt){
            float2 p = pb[qt];
            int id = __float_as_int(p.y);
            if (p.x > bv || (p.x == bv && id < bi)) { bv = p.x; bi = id; }
        }
        sidx[t] = bi;
        if (tail) tail[m*Qz + t] = (float)bi;
    }
    __syncthreads();
    if (t < 8){
        float p = g_hc2[t*Kz + sidx[t]];
        #pragma unroll
        for (int o = 4; o > 0; o >>= 1) p += __shfl_xor_sync(0xffu, p, o);
        if (t == 0){
            float mean = (2.0f*p) * (1.0f/1024.0f) + 1e-5f;
            float r = rsqrtf(mean);
            r = r * (1.5f - 0.5f*mean*r*r);
            s_scale = r;
        }
    }
    __syncthreads();
    int q = t >> 5, lane = t & 31;
    float4 c = reinterpret_cast<const float4*>(cb)[((size_t)q*Kz + sidx[q])*32 + lane];
    float sc = s_scale;
    float4 wv = reinterpret_cast<const float4*>(w)[t];
    reinterpret_cast<float4*>(out)[(size_t)m*256 + t] =
        make_float4(c.x*sc*wv.x, c.y*sc*wv.y, c.z*sc*wv.z, c.w*sc*wv.w);
}

// ---------------- Launch ----------------
extern "C" void kernel_launch(void* const* d_in, const int* in_sizes, int n_in,
                              void* d_out, int out_size){
    const float* x     = (const float*)d_in[0];
    const float* cb    = (const float*)d_in[1];
    const float* w_in  = (const float*)d_in[2];
    const float* w_out = (const float*)d_in[3];
    float* out = (float*)d_out;
    float* tail = (out_size >= OUT_ELEMS + IDX_ELEMS) ? (out + OUT_ELEMS) : nullptr;

    cudaFuncSetAttribute((const void*)argmin_kernel,
                         cudaFuncAttributeMaxDynamicSharedMemorySize, SMEM_ARGMIN);

    prep_kernel<<<Mz + (Qz*Kz)/8, 256>>>(x, cb);
    argmin_kernel<<<dim3((Mz/128)*4, Qz), 256, SMEM_ARGMIN>>>(x, w_in, cb);
    out_kernel<<<Mz, 256>>>(cb, w_out, out, tail);
}